// round 13
// baseline (speedup 1.0000x reference)
#include <cuda_runtime.h>
#include <cuda_bf16.h>
#include <math.h>
#include <stdint.h>

// Problem constants (fixed shapes)
#define BATCH 2
#define SEQ   2048
#define HID   2048
#define NH    16
#define NKV   4
#define GRP   4
#define HD    128
#define MROWS (BATCH*SEQ)     // 4096
#define KDIM  2048

typedef __nv_bfloat16 bf16;

// ---------------- scratch (device globals) ----------------------------------
__device__ float g_Pl1[MROWS*HID];
__device__ float g_pre[MROWS*HID];

__device__ __align__(16) bf16 g_srcH[MROWS*HID], g_srcL[MROWS*HID];
__device__ __align__(16) bf16 g_hidH[MROWS*HID], g_hidL[MROWS*HID];
__device__ __align__(16) bf16 g_Pl1H[MROWS*HID], g_Pl1L[MROWS*HID];
__device__ __align__(16) bf16 g_PH  [MROWS*HID], g_PL  [MROWS*HID];
__device__ __align__(16) bf16 g_ctxH[MROWS*HID], g_ctxL[MROWS*HID];

__device__ __align__(16) bf16 g_WqtH[HID*HID],      g_WqtL[HID*HID];
__device__ __align__(16) bf16 g_WktH[(NKV*HD)*HID], g_WktL[(NKV*HD)*HID];
__device__ __align__(16) bf16 g_WvtH[(NKV*HD)*HID], g_WvtL[(NKV*HD)*HID];
__device__ __align__(16) bf16 g_WdtH[HID*HID],      g_WdtL[HID*HID];
__device__ __align__(16) bf16 g_W1tH[HID*HID],      g_W1tL[HID*HID];
__device__ __align__(16) bf16 g_W2tH[HID*HID],      g_W2tL[HID*HID];

__device__ __align__(16) bf16 g_QH [MROWS*HID],      g_QL [MROWS*HID];     // ftile
__device__ __align__(16) bf16 g_KH [MROWS*NKV*HD],   g_KL [MROWS*NKV*HD];  // ftile
__device__ __align__(16) bf16 g_VtH[MROWS*NKV*HD],   g_VtL[MROWS*NKV*HD];  // vtile

// ================= helpers ==================================================
__device__ __forceinline__ void mma_bf16(float (&d)[4],
                                         const uint32_t* a, const uint32_t* b) {
    asm volatile(
        "mma.sync.aligned.m16n8k16.row.col.f32.bf16.bf16.f32 "
        "{%0,%1,%2,%3}, {%4,%5,%6,%7}, {%8,%9}, {%0,%1,%2,%3};\n"
        : "+f"(d[0]), "+f"(d[1]), "+f"(d[2]), "+f"(d[3])
        : "r"(a[0]), "r"(a[1]), "r"(a[2]), "r"(a[3]), "r"(b[0]), "r"(b[1]));
}

__device__ __forceinline__ void ldsm4(uint32_t* r, uint32_t addr) {
    asm volatile("ldmatrix.sync.aligned.m8n8.x4.shared.b16 {%0,%1,%2,%3}, [%4];"
        : "=r"(r[0]), "=r"(r[1]), "=r"(r[2]), "=r"(r[3]) : "r"(addr));
}

__device__ __forceinline__ float ex2(float x) {
    float y; asm("ex2.approx.ftz.f32 %0, %1;" : "=f"(y) : "f"(x)); return y;
}

__device__ __forceinline__ void split2(float v0, float v1,
                                       uint32_t& hi, uint32_t& lo) {
    __nv_bfloat162 h = __floats2bfloat162_rn(v0, v1);
    hi = *reinterpret_cast<uint32_t*>(&h);
    __nv_bfloat162 l = __floats2bfloat162_rn(v0 - __bfloat162float(h.x),
                                             v1 - __bfloat162float(h.y));
    lo = *reinterpret_cast<uint32_t*>(&l);
}

__device__ __forceinline__ uint32_t smem_u32(const void* p) {
    uint32_t a;
    asm("{ .reg .u64 t; cvta.to.shared.u64 t, %1; cvt.u32.u64 %0, t; }"
        : "=r"(a) : "l"(p));
    return a;
}

__device__ __forceinline__ void bulkcp(uint32_t dst, const void* src,
                                       uint32_t bytes, uint32_t mbar) {
    asm volatile(
        "cp.async.bulk.shared::cluster.global.mbarrier::complete_tx::bytes "
        "[%0], [%1], %2, [%3];"
        :: "r"(dst), "l"(src), "r"(bytes), "r"(mbar) : "memory");
}

#define MBAR_INIT(mbar, cnt) \
    asm volatile("mbarrier.init.shared.b64 [%0], %1;" \
                 :: "r"((uint32_t)(mbar)), "r"((uint32_t)(cnt)) : "memory")
#define MBAR_EXPECT(mbar, bytes) \
    asm volatile("mbarrier.arrive.expect_tx.shared.b64 _, [%0], %1;" \
                 :: "r"((uint32_t)(mbar)), "r"((uint32_t)(bytes)) : "memory")

#define MBAR_WAIT(mbar, par) do {                                              \
    uint32_t _m = (uint32_t)(mbar), _p = (uint32_t)(par), _d;                  \
    asm volatile("{\n\t.reg .pred p;\n\t"                                      \
        "mbarrier.try_wait.parity.acquire.cta.shared::cta.b64 p, [%1], %2;\n\t"\
        "selp.b32 %0, 1, 0, p;\n\t}" : "=r"(_d) : "r"(_m), "r"(_p) : "memory");\
    if (!_d) {                                                                 \
        asm volatile("{\n\t.reg .pred P1;\n\t"                                 \
            "WL_%=:\n\t"                                                       \
            "mbarrier.try_wait.parity.acquire.cta.shared::cta.b64 P1, [%0], %1, 0x989680;\n\t" \
            "@P1 bra.uni WD_%=;\n\t"                                           \
            "bra.uni WL_%=;\n\t"                                               \
            "WD_%=:\n\t}" :: "r"(_m), "r"(_p) : "memory");                     \
    } } while (0)

// ---- tiled-swizzled GEMM operand layout (8KB blocks) ------------------------
__device__ __forceinline__ size_t tiled_off(int r, int kchunk, int Kd) {
    int mb = r >> 7, kb = kchunk >> 2;
    int ri = r & 127, ci = kchunk & 3;
    int cs = ci ^ ((ri >> 1) & 3);
    return ((size_t)(mb * (Kd >> 5) + kb)) * 8192 + ri * 64 + cs * 16;
}

// ---- flash ftile / vtile layouts -------------------------------------------
__device__ __forceinline__ size_t ftile_off(int s, int d) {
    return (size_t)s * 256 + (size_t)(((d >> 3) ^ (s & 7)) << 4)
         + (size_t)(d & 7) * 2;
}
__device__ __forceinline__ size_t vtile_off(int d, int s) {
    int cc = s & 63;
    return (size_t)(s >> 6) * 16384 + (size_t)d * 128
         + (size_t)((((cc) >> 3) ^ (d & 7)) << 4) + (size_t)(cc & 7) * 2;
}

// ================= merged prep kernels ======================================
__global__ __launch_bounds__(256)
void split_all(const float* __restrict__ src, const float* __restrict__ hid,
               bf16* __restrict__ sH, bf16* __restrict__ sL,
               bf16* __restrict__ hH, bf16* __restrict__ hL, int n8)
{
    int i = blockIdx.x * blockDim.x + threadIdx.x;
    const float* x; bf16 *hip, *lop;
    if (i >= n8) { i -= n8; x = hid; hip = hH; lop = hL; }
    else         {          x = src; hip = sH; lop = sL; }
    int r  = i >> 8;
    int kc = i & 255;
    const float4* xp = (const float4*)x + (size_t)i * 2;
    float4 v0 = xp[0], v1 = xp[1];
    uint32_t h0,l0,h1,l1,h2,l2,h3,l3;
    split2(v0.x, v0.y, h0, l0); split2(v0.z, v0.w, h1, l1);
    split2(v1.x, v1.y, h2, l2); split2(v1.z, v1.w, h3, l3);
    size_t o = tiled_off(r, kc, 2048);
    *(uint4*)((char*)hip + o) = make_uint4(h0, h1, h2, h3);
    *(uint4*)((char*)lop + o) = make_uint4(l0, l1, l2, l3);
}

__global__ __launch_bounds__(256)
void tsplit_all(const float* W1, const float* W2, const float* Wk,
                const float* Wv, const float* Wq, const float* Wd,
                bf16* T1H, bf16* T1L, bf16* T2H, bf16* T2L,
                bf16* TkH, bf16* TkL, bf16* TvH, bf16* TvL,
                bf16* TqH, bf16* TqL, bf16* TdH, bf16* TdL)
{
    const float* Wt[6] = { W1, W2, Wk, Wv, Wq, Wd };
    bf16* THt[6] = { T1H, T2H, TkH, TvH, TqH, TdH };
    bf16* TLt[6] = { T1L, T2L, TkL, TvL, TqL, TdL };
    const int Ndt[6] = { 2048, 2048, 512, 512, 2048, 2048 };
    int z = blockIdx.z;
    const float* W = Wt[z];
    bf16* TH = THt[z];
    bf16* TL = TLt[z];
    int Nd = Ndt[z];
    int n0 = blockIdx.x * 32;
    if (n0 >= Nd) return;
    int k0 = blockIdx.y * 32;

    __shared__ float tl[32][33];
    int tx = threadIdx.x & 31;
    int ty = threadIdx.x >> 5;
    #pragma unroll
    for (int i = 0; i < 4; i++)
        tl[ty + 8*i][tx] = W[(size_t)(k0 + ty + 8*i) * Nd + n0 + tx];
    __syncthreads();
    #pragma unroll
    for (int i = 0; i < 4; i++) {
        float v = tl[tx][ty + 8*i];
        bf16 h = __float2bfloat16(v);
        int n_ = n0 + ty + 8*i, k_ = k0 + tx;
        size_t o = tiled_off(n_, k_ >> 3, 2048) + (size_t)(k_ & 7) * 2;
        *(bf16*)((char*)TH + o) = h;
        *(bf16*)((char*)TL + o) = __float2bfloat16(v - __bfloat162float(h));
    }
}

// ================= persistent bulk-load split-bf16 tensor GEMM ==============
// Tile 128x128, ktile 32, 8 warps (m64 x n32), 3-stage ring continuous across
// tiles, 2 CTAs/SM. Two tile groups (for merged K+V launch).
#define TPL   8192
#define TSTG  (4*TPL)                 // 32768
#define NSTG  3
#define TC_SMEM (64 + NSTG*TSTG)      // 98368
#define NKT   (KDIM/32)               // 64 ktiles per tile

#define M_RELU   1
#define M_RES    2
#define M_WRITEC 8
#define M_SPLIT  16
#define M_FSCAT  32
#define M_VSCAT  64

__global__ __launch_bounds__(256, 2)
void bgemm_kernel(const bf16* __restrict__ AH, const bf16* __restrict__ AL,
                  const bf16* __restrict__ B1H, const bf16* __restrict__ B1L,
                  const bf16* __restrict__ B2H, const bf16* __restrict__ B2L,
                  const float* __restrict__ bias1, const float* __restrict__ bias2,
                  const float* __restrict__ res,
                  float* __restrict__ C,
                  bf16* __restrict__ C1H, bf16* __restrict__ C1L,
                  bf16* __restrict__ C2H, bf16* __restrict__ C2L,
                  int N, int mode1, int mode2, int heads,
                  int gx, int numTiles, int tileSplit)
{
    extern __shared__ char smraw[];
    const uint32_t sb   = smem_u32(smraw);
    const uint32_t fulb = sb;
    const uint32_t sb0  = sb + 64;

    const int tid  = threadIdx.x;
    const int wid  = tid >> 5;
    const int lane = tid & 31;
    const int l15  = lane & 15;
    const int lsel = lane >> 4;
    const int warpM = (wid & 1) * 64;
    const int warpN = (wid >> 1) * 32;

    if (tid == 0) {
        #pragma unroll
        for (int s = 0; s < NSTG; s++) MBAR_INIT(fulb + s * 8, 1);
    }
    __syncthreads();

    const int myTiles = (numTiles - blockIdx.x + gridDim.x - 1) / gridDim.x;
    if (myTiles <= 0) return;
    const int totalG = myTiles * NKT;

    // stage loader: global stage index g -> (tile slot, kt)
#define TLOAD(g_, st_) do {                                                    \
        int slot_ = (g_) / NKT, kt_ = (g_) % NKT;                              \
        int ti_ = blockIdx.x + slot_ * gridDim.x;                              \
        int grp_ = (ti_ >= tileSplit);                                         \
        int tl_ = grp_ ? ti_ - tileSplit : ti_;                                \
        int bx_ = tl_ % gx, by_ = tl_ / gx;                                    \
        const bf16* BH_ = grp_ ? B2H : B1H;                                    \
        const bf16* BL_ = grp_ ? B2L : B1L;                                    \
        MBAR_EXPECT(fulb + (st_)*8, (uint32_t)TSTG);                           \
        uint32_t sp_ = sb0 + (st_)*TSTG;                                       \
        size_t ao_ = ((size_t)(by_ * 64 + kt_)) * TPL;                         \
        size_t bo_ = ((size_t)(bx_ * 64 + kt_)) * TPL;                         \
        bulkcp(sp_,           (const char*)AH  + ao_, TPL, fulb + (st_)*8);    \
        bulkcp(sp_ +   TPL,   (const char*)AL  + ao_, TPL, fulb + (st_)*8);    \
        bulkcp(sp_ + 2*TPL,   (const char*)BH_ + bo_, TPL, fulb + (st_)*8);    \
        bulkcp(sp_ + 3*TPL,   (const char*)BL_ + bo_, TPL, fulb + (st_)*8);    \
    } while (0)

    if (tid == 0) {
        #pragma unroll
        for (int s = 0; s < NSTG; s++)
            if (s < totalG) TLOAD(s, s);
    }

    float acc[4][4][4];
    #pragma unroll
    for (int i = 0; i < 4; i++)
        #pragma unroll
        for (int j = 0; j < 4; j++)
            #pragma unroll
            for (int c = 0; c < 4; c++) acc[i][j][c] = 0.f;

    const int g_  = lane >> 2;
    const int t4  = lane & 3;

    for (int g = 0; g < totalG; g++) {
        const int st = g % NSTG;
        MBAR_WAIT(fulb + st * 8, (g / NSTG) & 1);
        const uint32_t sp = sb0 + st * TSTG;

        #pragma unroll
        for (int ks = 0; ks < 2; ks++) {
            uint32_t ah[4][4], al[4][4], bh[4][2], bl[4][2];
            #pragma unroll
            for (int mi = 0; mi < 4; mi++) {
                int ar = warpM + mi * 16 + l15;
                uint32_t ad = sp + ar * 64
                            + (((ks * 2 + lsel) ^ ((ar >> 1) & 3)) << 4);
                ldsm4(ah[mi], ad);
                ldsm4(al[mi], ad + TPL);
            }
            #pragma unroll
            for (int n2 = 0; n2 < 2; n2++) {
                int br = warpN + n2 * 16 + l15;
                uint32_t bd = sp + 2*TPL + br * 64
                            + (((ks * 2 + lsel) ^ ((br >> 1) & 3)) << 4);
                uint32_t r[4];
                ldsm4(r, bd);
                bh[2*n2][0]   = r[0]; bh[2*n2][1]   = r[2];
                bh[2*n2+1][0] = r[1]; bh[2*n2+1][1] = r[3];
                ldsm4(r, bd + TPL);
                bl[2*n2][0]   = r[0]; bl[2*n2][1]   = r[2];
                bl[2*n2+1][0] = r[1]; bl[2*n2+1][1] = r[3];
            }
            #pragma unroll
            for (int mi = 0; mi < 4; mi++)
                #pragma unroll
                for (int ni = 0; ni < 4; ni++) {
                    mma_bf16(acc[mi][ni], al[mi], bh[ni]);
                    mma_bf16(acc[mi][ni], ah[mi], bl[ni]);
                    mma_bf16(acc[mi][ni], ah[mi], bh[ni]);
                }
        }

        __syncthreads();
        if (tid == 0 && g + NSTG < totalG) TLOAD(g + NSTG, st);

        // ---- tile boundary: epilogue + acc reset ----
        if ((g % NKT) == NKT - 1) {
            int ti  = blockIdx.x + (g / NKT) * gridDim.x;
            int grp = (ti >= tileSplit);
            int tl  = grp ? ti - tileSplit : ti;
            int bx  = tl % gx, by = tl / gx;
            const int mode = grp ? mode2 : mode1;
            const float* bias = grp ? bias2 : bias1;
            bf16* CH = grp ? C2H : C1H;
            bf16* CL = grp ? C2L : C1L;
            const int mBase = by * 128, nBase = bx * 128;
            const int rw = mBase + warpM + g_;
            const int cw = nBase + warpN + 2 * t4;
            #pragma unroll
            for (int mi = 0; mi < 4; mi++) {
                #pragma unroll
                for (int h = 0; h < 2; h++) {
                    const int r = rw + mi * 16 + h * 8;
                    const int b = r / SEQ, s = r - (r / SEQ) * SEQ;
                    #pragma unroll
                    for (int ni = 0; ni < 4; ni++) {
                        const int c0 = cw + ni * 8;
                        float v0 = acc[mi][ni][h*2 + 0] + bias[c0];
                        float v1 = acc[mi][ni][h*2 + 1] + bias[c0 + 1];
                        if (mode & M_RELU) { v0 = fmaxf(v0, 0.f); v1 = fmaxf(v1, 0.f); }
                        if (mode & M_RES) {
                            v0 += res[(size_t)r * N + c0];
                            v1 += res[(size_t)r * N + c0 + 1];
                        }
                        if (mode & M_WRITEC) {
                            C[(size_t)r * N + c0]     = v0;
                            C[(size_t)r * N + c0 + 1] = v1;
                        }
                        if (mode & (M_SPLIT | M_FSCAT | M_VSCAT)) {
                            uint32_t hi, lo;
                            split2(v0, v1, hi, lo);
                            if (mode & M_SPLIT) {
                                size_t o = tiled_off(r, c0 >> 3, 2048)
                                         + (size_t)(c0 & 7) * 2;
                                *(uint32_t*)((char*)CH + o) = hi;
                                *(uint32_t*)((char*)CL + o) = lo;
                            } else if (mode & M_FSCAT) {
                                int head = c0 >> 7, d = c0 & 127;
                                size_t hb = ((size_t)(b * heads + head)) * SEQ * HD * 2;
                                size_t o = hb + ftile_off(s, d);
                                *(uint32_t*)((char*)CH + o) = hi;
                                *(uint32_t*)((char*)CL + o) = lo;
                            } else {
                                int head = c0 >> 7, d = c0 & 127;
                                size_t hb = ((size_t)(b * NKV + head)) * HD * SEQ * 2;
                                size_t o0 = hb + vtile_off(d,     s);
                                size_t o1 = hb + vtile_off(d + 1, s);
                                __nv_bfloat162 H = *reinterpret_cast<__nv_bfloat162*>(&hi);
                                __nv_bfloat162 L = *reinterpret_cast<__nv_bfloat162*>(&lo);
                                *(bf16*)((char*)CH + o0) = H.x;
                                *(bf16*)((char*)CH + o1) = H.y;
                                *(bf16*)((char*)CL + o0) = L.x;
                                *(bf16*)((char*)CL + o1) = L.y;
                            }
                        }
                    }
                }
            }
            #pragma unroll
            for (int i = 0; i < 4; i++)
                #pragma unroll
                for (int j = 0; j < 4; j++)
                    #pragma unroll
                    for (int c = 0; c < 4; c++) acc[i][j][c] = 0.f;
        }
    }
#undef TLOAD
}

// ================= tensor-core flash attention (big bulk loads) =============
#define OFF_Q  0
#define FQPL   32768
#define OFF_K  (2*FQPL)
#define FKST   32768
#define OFF_V  (OFF_K + 2*FKST)
#define FVST   32768
#define OFF_MB (OFF_V + 2*FVST)
#define FSMEM  (OFF_MB + 64)

__global__ __launch_bounds__(256, 1)
void flash2_kernel(const bf16* __restrict__ QH, const bf16* __restrict__ QL,
                   const bf16* __restrict__ KH, const bf16* __restrict__ KL,
                   const bf16* __restrict__ VtH, const bf16* __restrict__ VtL,
                   bf16* __restrict__ ctxH, bf16* __restrict__ ctxL)
{
    extern __shared__ char smraw[];
    const uint32_t sb  = smem_u32(smraw);
    const uint32_t fmb = sb + OFF_MB;

    const int tid  = threadIdx.x;
    const int wid  = tid >> 5;
    const int lane = tid & 31;
    const int g    = lane >> 2;
    const int t4   = lane & 3;
    const int l15  = lane & 15;
    const int lsel = lane >> 4;

    const int qb = blockIdx.x;
    const int bh = blockIdx.y;
    const int b  = bh / NH;
    const int h  = bh % NH;
    const int kv = b * NKV + (h / GRP);

    const char* Qhb  = (const char*)QH  + (size_t)bh * SEQ * HD * 2;
    const char* Qlb  = (const char*)QL  + (size_t)bh * SEQ * HD * 2;
    const char* Khb  = (const char*)KH  + (size_t)kv * SEQ * HD * 2;
    const char* Klb  = (const char*)KL  + (size_t)kv * SEQ * HD * 2;
    const char* Vthb = (const char*)VtH + (size_t)kv * HD * SEQ * 2;
    const char* Vtlb = (const char*)VtL + (size_t)kv * HD * SEQ * 2;

    if (tid == 0) { MBAR_INIT(fmb, 1); MBAR_INIT(fmb + 8, 1); }
    __syncthreads();

#define LOADKV(kc, st) do { if (tid == 0) {                                    \
        MBAR_EXPECT(fmb + (st)*8, 65536);                                      \
        size_t kb_ = (size_t)(kc) * 256;                                       \
        size_t vb_ = (size_t)((kc) >> 6) * 16384;                              \
        bulkcp(sb + OFF_K + (st)*FKST,          Khb  + kb_, 16384, fmb + (st)*8); \
        bulkcp(sb + OFF_K + (st)*FKST + 16384,  Klb  + kb_, 16384, fmb + (st)*8); \
        bulkcp(sb + OFF_V + (st)*FVST,          Vthb + vb_, 16384, fmb + (st)*8); \
        bulkcp(sb + OFF_V + (st)*FVST + 16384,  Vtlb + vb_, 16384, fmb + (st)*8); \
    } } while (0)

    if (tid == 0) {
        MBAR_EXPECT(fmb, 131072);
        bulkcp(sb + OFF_Q,        Qhb + (size_t)qb * 32768, 32768, fmb);
        bulkcp(sb + OFF_Q + FQPL, Qlb + (size_t)qb * 32768, 32768, fmb);
        bulkcp(sb + OFF_K,          Khb,  16384, fmb);
        bulkcp(sb + OFF_K + 16384,  Klb,  16384, fmb);
        bulkcp(sb + OFF_V,          Vthb, 16384, fmb);
        bulkcp(sb + OFF_V + 16384,  Vtlb, 16384, fmb);
    }

    const int m0r = wid * 16;
    float O[16][4];
    #pragma unroll
    for (int j = 0; j < 16; j++)
        #pragma unroll
        for (int c = 0; c < 4; c++) O[j][c] = 0.f;
    float mrow0 = -1e30f, mrow1 = -1e30f, lrow0 = 0.f, lrow1 = 0.f;
    const float c1 = 0.08838834764831845f * 1.4426950408889634f;

    for (int ic = 0; ic < SEQ / 64; ic++) {
        const int buf = ic & 1;
        if (ic + 1 < SEQ / 64) LOADKV((ic + 1) * 64, buf ^ 1);
        MBAR_WAIT(fmb + buf * 8, (ic >> 1) & 1);

        float s_[8][4];
        #pragma unroll
        for (int j = 0; j < 8; j++)
            #pragma unroll
            for (int c = 0; c < 4; c++) s_[j][c] = 0.f;

        const uint32_t kbase = sb + OFF_K + buf * FKST;
        #pragma unroll
        for (int kk = 0; kk < 8; kk++) {
            uint32_t aH[4], aL[4];
            int qr = m0r + l15;
            uint32_t aoq = (uint32_t)(qr * 256
                         + (((kk * 2 + lsel) ^ (qr & 7)) << 4));
            ldsm4(aH, sb + OFF_Q + aoq);
            ldsm4(aL, sb + OFF_Q + FQPL + aoq);
            #pragma unroll
            for (int j2 = 0; j2 < 4; j2++) {
                int kr = j2 * 16 + l15;
                uint32_t bo = (uint32_t)(kr * 256
                            + (((kk * 2 + lsel) ^ (kr & 7)) << 4));
                uint32_t rH[4], rL[4];
                ldsm4(rH, kbase + bo);
                ldsm4(rL, kbase + 16384 + bo);
                uint32_t bh0[2] = { rH[0], rH[2] }, bh1[2] = { rH[1], rH[3] };
                uint32_t bl0[2] = { rL[0], rL[2] }, bl1[2] = { rL[1], rL[3] };
                mma_bf16(s_[2*j2],   aL, bh0);
                mma_bf16(s_[2*j2],   aH, bl0);
                mma_bf16(s_[2*j2],   aH, bh0);
                mma_bf16(s_[2*j2+1], aL, bh1);
                mma_bf16(s_[2*j2+1], aH, bl1);
                mma_bf16(s_[2*j2+1], aH, bh1);
            }
        }

        float zx0 = -1e30f, zx1 = -1e30f;
        #pragma unroll
        for (int j = 0; j < 8; j++) {
            zx0 = fmaxf(zx0, fmaxf(s_[j][0], s_[j][1]));
            zx1 = fmaxf(zx1, fmaxf(s_[j][2], s_[j][3]));
        }
        zx0 *= c1; zx1 *= c1;
        #pragma unroll
        for (int w = 1; w <= 2; w <<= 1) {
            zx0 = fmaxf(zx0, __shfl_xor_sync(0xffffffffu, zx0, w));
            zx1 = fmaxf(zx1, __shfl_xor_sync(0xffffffffu, zx1, w));
        }
        float mn0 = fmaxf(mrow0, zx0), mn1 = fmaxf(mrow1, zx1);
        float al0 = ex2(mrow0 - mn0),  al1 = ex2(mrow1 - mn1);
        float rs0 = 0.f, rs1 = 0.f;
        #pragma unroll
        for (int j = 0; j < 8; j++) {
            s_[j][0] = ex2(fmaf(s_[j][0], c1, -mn0));
            s_[j][1] = ex2(fmaf(s_[j][1], c1, -mn0));
            s_[j][2] = ex2(fmaf(s_[j][2], c1, -mn1));
            s_[j][3] = ex2(fmaf(s_[j][3], c1, -mn1));
            rs0 += s_[j][0] + s_[j][1];
            rs1 += s_[j][2] + s_[j][3];
        }
        #pragma unroll
        for (int w = 1; w <= 2; w <<= 1) {
            rs0 += __shfl_xor_sync(0xffffffffu, rs0, w);
            rs1 += __shfl_xor_sync(0xffffffffu, rs1, w);
        }
        lrow0 = lrow0 * al0 + rs0;
        lrow1 = lrow1 * al1 + rs1;
        mrow0 = mn0; mrow1 = mn1;

        #pragma unroll
        for (int j = 0; j < 16; j++) {
            O[j][0] *= al0; O[j][1] *= al0;
            O[j][2] *= al1; O[j][3] *= al1;
        }

        uint32_t ph[4][4], pl[4][4];
        #pragma unroll
        for (int kk = 0; kk < 4; kk++) {
            split2(s_[2*kk][0],   s_[2*kk][1],   ph[kk][0], pl[kk][0]);
            split2(s_[2*kk][2],   s_[2*kk][3],   ph[kk][1], pl[kk][1]);
            split2(s_[2*kk+1][0], s_[2*kk+1][1], ph[kk][2], pl[kk][2]);
            split2(s_[2*kk+1][2], s_[2*kk+1][3], ph[kk][3], pl[kk][3]);
        }

        const uint32_t vbase = sb + OFF_V + buf * FVST;
        #pragma unroll
        for (int kk = 0; kk < 4; kk++) {
            #pragma unroll
            for (int j2 = 0; j2 < 8; j2++) {
                int vr = j2 * 16 + l15;
                uint32_t vo = (uint32_t)(vr * 128
                            + (((kk * 2 + lsel) ^ (vr & 7)) << 4));
                uint32_t rH[4], rL[4];
                ldsm4(rH, vbase + vo);
                ldsm4(rL, vbase + 16384 + vo);
                uint32_t bh0[2] = { rH[0], rH[2] }, bh1[2] = { rH[1], rH[3] };
                uint32_t bl0[2] = { rL[0], rL[2] }, bl1[2] = { rL[1], rL[3] };
                mma_bf16(O[2*j2],   pl[kk], bh0);
                mma_bf16(O[2*j2],   ph[kk], bl0);
                mma_bf16(O[2*j2],   ph[kk], bh0);
                mma_bf16(O[2*j2+1], pl[kk], bh1);
                mma_bf16(O[2*j2+1], ph[kk], bl1);
                mma_bf16(O[2*j2+1], ph[kk], bh1);
            }
        }
        __syncthreads();
    }
#undef LOADKV

    const float inv0 = 1.f / lrow0, inv1 = 1.f / lrow1;
    const int q0 = qb * 128 + m0r + g;
    const int q1 = q0 + 8;
    const int row0 = b * SEQ + q0;
    const int row1 = b * SEQ + q1;
    #pragma unroll
    for (int j = 0; j < 16; j++) {
        const int colg = h * HD + j * 8 + 2 * t4;
        uint32_t hi, lo;
        split2(O[j][0] * inv0, O[j][1] * inv0, hi, lo);
        size_t o0 = tiled_off(row0, colg >> 3, 2048) + (size_t)(colg & 7) * 2;
        *(uint32_t*)((char*)ctxH + o0) = hi;
        *(uint32_t*)((char*)ctxL + o0) = lo;
        split2(O[j][2] * inv1, O[j][3] * inv1, hi, lo);
        size_t o1 = tiled_off(row1, colg >> 3, 2048) + (size_t)(colg & 7) * 2;
        *(uint32_t*)((char*)ctxH + o1) = hi;
        *(uint32_t*)((char*)ctxL + o1) = lo;
    }
}

// ---------------- residual + layernorm -------------------------------------
__device__ __forceinline__ float block_sum256(float v, float* sred)
{
    #pragma unroll
    for (int off = 16; off; off >>= 1) v += __shfl_xor_sync(0xffffffffu, v, off);
    int warp = threadIdx.x >> 5;
    if ((threadIdx.x & 31) == 0) sred[warp] = v;
    __syncthreads();
    if (threadIdx.x < 32) {
        float x = (threadIdx.x < 8) ? sred[threadIdx.x] : 0.f;
        #pragma unroll
        for (int off = 4; off; off >>= 1) x += __shfl_xor_sync(0xffffffffu, x, off);
        if (threadIdx.x == 0) sred[0] = x;
    }
    __syncthreads();
    float r = sred[0];
    __syncthreads();
    return r;
}

__global__ __launch_bounds__(256)
void ln_kernel(const float* __restrict__ x, const float* __restrict__ resid,
               const float* __restrict__ gamma, const float* __restrict__ beta,
               float* __restrict__ out)
{
    __shared__ float sred[32];
    const size_t row = blockIdx.x;
    const int tid = threadIdx.x;
    const float* xr = x     + row * HID;
    const float* rr = resid + row * HID;

    float v[8];
    float s = 0.f;
    #pragma unroll
    for (int t = 0; t < 8; t++) {
        int c = tid + t * 256;
        v[t] = xr[c] + rr[c];
        s += v[t];
    }
    float mean = block_sum256(s, sred) * (1.f / HID);

    float s2 = 0.f;
    #pragma unroll
    for (int t = 0; t < 8; t++) { float d = v[t] - mean; s2 += d * d; }
    float var = block_sum256(s2, sred) * (1.f / HID);
    float rstd = rsqrtf(var + 1e-12f);

    float* orow = out + row * HID;
    #pragma unroll
    for (int t = 0; t < 8; t++) {
        int c = tid + t * 256;
        orow[c] = (v[t] - mean) * rstd * gamma[c] + beta[c];
    }
}

// ---------------- launch ----------------------------------------------------
extern "C" void kernel_launch(void* const* d_in, const int* in_sizes, int n_in,
                              void* d_out, int out_size)
{
    const float* hidden = (const float*)d_in[0];
    const float* src    = (const float*)d_in[1];
    const float* Wq = (const float*)d_in[2];
    const float* bq = (const float*)d_in[3];
    const float* Wk = (const float*)d_in[4];
    const float* bk = (const float*)d_in[5];
    const float* Wv = (const float*)d_in[6];
    const float* bv = (const float*)d_in[7];
    const float* Wd = (const float*)d_in[8];
    const float* bd = (const float*)d_in[9];
    const float* W1 = (const float*)d_in[10];
    const float* b1 = (const float*)d_in[11];
    const float* W2 = (const float*)d_in[12];
    const float* b2 = (const float*)d_in[13];
    const float* gamma = (const float*)d_in[14];
    const float* beta  = (const float*)d_in[15];
    float* out = (float*)d_out;

    float *pPl1, *pPre;
    cudaGetSymbolAddress((void**)&pPl1, g_Pl1);
    cudaGetSymbolAddress((void**)&pPre, g_pre);

    bf16 *srcH,*srcL,*hidH,*hidL,*Pl1H,*Pl1L,*PH,*PL,*ctxH,*ctxL;
    bf16 *QH,*QL,*KHp,*KLp,*VtHp,*VtLp;
    cudaGetSymbolAddress((void**)&srcH, g_srcH); cudaGetSymbolAddress((void**)&srcL, g_srcL);
    cudaGetSymbolAddress((void**)&hidH, g_hidH); cudaGetSymbolAddress((void**)&hidL, g_hidL);
    cudaGetSymbolAddress((void**)&Pl1H, g_Pl1H); cudaGetSymbolAddress((void**)&Pl1L, g_Pl1L);
    cudaGetSymbolAddress((void**)&PH,   g_PH);   cudaGetSymbolAddress((void**)&PL,   g_PL);
    cudaGetSymbolAddress((void**)&ctxH, g_ctxH); cudaGetSymbolAddress((void**)&ctxL, g_ctxL);
    cudaGetSymbolAddress((void**)&QH,   g_QH);   cudaGetSymbolAddress((void**)&QL,   g_QL);
    cudaGetSymbolAddress((void**)&KHp,  g_KH);   cudaGetSymbolAddress((void**)&KLp,  g_KL);
    cudaGetSymbolAddress((void**)&VtHp, g_VtH);  cudaGetSymbolAddress((void**)&VtLp, g_VtL);

    bf16 *WqtH,*WqtL,*WktH,*WktL,*WvtH,*WvtL,*WdtH,*WdtL,*W1tH,*W1tL,*W2tH,*W2tL;
    cudaGetSymbolAddress((void**)&WqtH, g_WqtH); cudaGetSymbolAddress((void**)&WqtL, g_WqtL);
    cudaGetSymbolAddress((void**)&WktH, g_WktH); cudaGetSymbolAddress((void**)&WktL, g_WktL);
    cudaGetSymbolAddress((void**)&WvtH, g_WvtH); cudaGetSymbolAddress((void**)&WvtL, g_WvtL);
    cudaGetSymbolAddress((void**)&WdtH, g_WdtH); cudaGetSymbolAddress((void**)&WdtL, g_WdtL);
    cudaGetSymbolAddress((void**)&W1tH, g_W1tH); cudaGetSymbolAddress((void**)&W1tL, g_W1tL);
    cudaGetSymbolAddress((void**)&W2tH, g_W2tH); cudaGetSymbolAddress((void**)&W2tL, g_W2tL);

    cudaFuncSetAttribute(bgemm_kernel, cudaFuncAttributeMaxDynamicSharedMemorySize, TC_SMEM);
    cudaFuncSetAttribute(flash2_kernel, cudaFuncAttributeMaxDynamicSharedMemorySize, FSMEM);

    dim3 blk(256);
    const int n8 = MROWS * HID / 8;
    const int PG = 296;   // persistent grid: 148 SMs x 2 CTAs

    // launch 0/1: prep
    split_all<<<2 * n8 / 256, blk>>>(src, hidden, srcH, srcL, hidH, hidL, n8);
    tsplit_all<<<dim3(64, 64, 6), blk>>>(W1, W2, Wk, Wv, Wq, Wd,
                                         W1tH, W1tL, W2tH, W2tL,
                                         WktH, WktL, WvtH, WvtL,
                                         WqtH, WqtL, WdtH, WdtL);

    // launch 2: Pl1 = relu(src @ W1 + b1)   [512 tiles persistent]
    bgemm_kernel<<<PG, blk, TC_SMEM>>>(
        srcH, srcL, W1tH, W1tL, W1tH, W1tL, b1, b1, nullptr,
        pPl1, Pl1H, Pl1L, Pl1H, Pl1L,
        HID, M_RELU | M_WRITEC | M_SPLIT, 0, 0, 16, 512, 512);
    // launch 3: P = (Pl1 @ W2 + b2) + Pl1
    bgemm_kernel<<<PG, blk, TC_SMEM>>>(
        Pl1H, Pl1L, W2tH, W2tL, W2tH, W2tL, b2, b2, pPl1,
        nullptr, PH, PL, PH, PL,
        HID, M_RES | M_SPLIT, 0, 0, 16, 512, 512);
    // launch 4: merged K (ftile) + V (vtile)  [128 + 128 tiles, one wave]
    bgemm_kernel<<<256, blk, TC_SMEM>>>(
        PH, PL, WktH, WktL, WvtH, WvtL, bk, bv, nullptr,
        nullptr, KHp, KLp, VtHp, VtLp,
        NKV*HD, M_FSCAT, M_VSCAT, NKV, 4, 256, 128);
    // launch 5: Q -> ftile
    bgemm_kernel<<<PG, blk, TC_SMEM>>>(
        hidH, hidL, WqtH, WqtL, WqtH, WqtL, bq, bq, nullptr,
        nullptr, QH, QL, QH, QL,
        HID, M_FSCAT, 0, NH, 16, 512, 512);
    // launch 6: flash attention
    flash2_kernel<<<dim3(SEQ/128, BATCH*NH), blk, FSMEM>>>(
        QH, QL, KHp, KLp, VtHp, VtLp, ctxH, ctxL);
    // launch 7: pre = ctx @ Wd + bd
    bgemm_kernel<<<PG, blk, TC_SMEM>>>(
        ctxH, ctxL, WdtH, WdtL, WdtH, WdtL, bd, bd, nullptr,
        pPre, nullptr, nullptr, nullptr, nullptr,
        HID, M_WRITEC, 0, 0, 16, 512, 512);
    // launch 8: out = layernorm(pre + hidden)
    ln_kernel<<<MROWS, 256>>>(pPre, hidden, gamma, beta, out);
}

// round 16
// speedup vs baseline: 1.0301x; 1.0301x over previous
#include <cuda_runtime.h>
#include <cuda_bf16.h>
#include <math.h>
#include <stdint.h>

// Problem constants (fixed shapes)
#define BATCH 2
#define SEQ   2048
#define HID   2048
#define NH    16
#define NKV   4
#define GRP   4
#define HD    128
#define MROWS (BATCH*SEQ)     // 4096
#define KDIM  2048

typedef __nv_bfloat16 bf16;

// ---------------- scratch (device globals) ----------------------------------
__device__ float g_Pl1[MROWS*HID];
__device__ float g_pre[MROWS*HID];

__device__ __align__(16) bf16 g_srcH[MROWS*HID], g_srcL[MROWS*HID];
__device__ __align__(16) bf16 g_hidH[MROWS*HID], g_hidL[MROWS*HID];
__device__ __align__(16) bf16 g_Pl1H[MROWS*HID], g_Pl1L[MROWS*HID];
__device__ __align__(16) bf16 g_PH  [MROWS*HID], g_PL  [MROWS*HID];
__device__ __align__(16) bf16 g_ctxH[MROWS*HID], g_ctxL[MROWS*HID];

__device__ __align__(16) bf16 g_WqtH[HID*HID],      g_WqtL[HID*HID];
__device__ __align__(16) bf16 g_WktH[(NKV*HD)*HID], g_WktL[(NKV*HD)*HID];
__device__ __align__(16) bf16 g_WvtH[(NKV*HD)*HID], g_WvtL[(NKV*HD)*HID];
__device__ __align__(16) bf16 g_WdtH[HID*HID],      g_WdtL[HID*HID];
__device__ __align__(16) bf16 g_W1tH[HID*HID],      g_W1tL[HID*HID];
__device__ __align__(16) bf16 g_W2tH[HID*HID],      g_W2tL[HID*HID];

__device__ __align__(16) bf16 g_QH [MROWS*HID],      g_QL [MROWS*HID];     // ftile
__device__ __align__(16) bf16 g_KH [MROWS*NKV*HD],   g_KL [MROWS*NKV*HD];  // ftile
__device__ __align__(16) bf16 g_VtH[MROWS*NKV*HD],   g_VtL[MROWS*NKV*HD];  // vtile

// ================= helpers ==================================================
__device__ __forceinline__ void mma_bf16(float (&d)[4],
                                         const uint32_t* a, const uint32_t* b) {
    asm volatile(
        "mma.sync.aligned.m16n8k16.row.col.f32.bf16.bf16.f32 "
        "{%0,%1,%2,%3}, {%4,%5,%6,%7}, {%8,%9}, {%0,%1,%2,%3};\n"
        : "+f"(d[0]), "+f"(d[1]), "+f"(d[2]), "+f"(d[3])
        : "r"(a[0]), "r"(a[1]), "r"(a[2]), "r"(a[3]), "r"(b[0]), "r"(b[1]));
}

__device__ __forceinline__ void ldsm4(uint32_t* r, uint32_t addr) {
    asm volatile("ldmatrix.sync.aligned.m8n8.x4.shared.b16 {%0,%1,%2,%3}, [%4];"
        : "=r"(r[0]), "=r"(r[1]), "=r"(r[2]), "=r"(r[3]) : "r"(addr));
}

__device__ __forceinline__ float ex2(float x) {
    float y; asm("ex2.approx.ftz.f32 %0, %1;" : "=f"(y) : "f"(x)); return y;
}

__device__ __forceinline__ void split2(float v0, float v1,
                                       uint32_t& hi, uint32_t& lo) {
    __nv_bfloat162 h = __floats2bfloat162_rn(v0, v1);
    hi = *reinterpret_cast<uint32_t*>(&h);
    __nv_bfloat162 l = __floats2bfloat162_rn(v0 - __bfloat162float(h.x),
                                             v1 - __bfloat162float(h.y));
    lo = *reinterpret_cast<uint32_t*>(&l);
}

__device__ __forceinline__ uint32_t smem_u32(const void* p) {
    uint32_t a;
    asm("{ .reg .u64 t; cvta.to.shared.u64 t, %1; cvt.u32.u64 %0, t; }"
        : "=r"(a) : "l"(p));
    return a;
}

__device__ __forceinline__ void bulkcp(uint32_t dst, const void* src,
                                       uint32_t bytes, uint32_t mbar) {
    asm volatile(
        "cp.async.bulk.shared::cluster.global.mbarrier::complete_tx::bytes "
        "[%0], [%1], %2, [%3];"
        :: "r"(dst), "l"(src), "r"(bytes), "r"(mbar) : "memory");
}

#define MBAR_INIT(mbar, cnt) \
    asm volatile("mbarrier.init.shared.b64 [%0], %1;" \
                 :: "r"((uint32_t)(mbar)), "r"((uint32_t)(cnt)) : "memory")
#define MBAR_EXPECT(mbar, bytes) \
    asm volatile("mbarrier.arrive.expect_tx.shared.b64 _, [%0], %1;" \
                 :: "r"((uint32_t)(mbar)), "r"((uint32_t)(bytes)) : "memory")

#define MBAR_WAIT(mbar, par) do {                                              \
    uint32_t _m = (uint32_t)(mbar), _p = (uint32_t)(par), _d;                  \
    asm volatile("{\n\t.reg .pred p;\n\t"                                      \
        "mbarrier.try_wait.parity.acquire.cta.shared::cta.b64 p, [%1], %2;\n\t"\
        "selp.b32 %0, 1, 0, p;\n\t}" : "=r"(_d) : "r"(_m), "r"(_p) : "memory");\
    if (!_d) {                                                                 \
        asm volatile("{\n\t.reg .pred P1;\n\t"                                 \
            "WL_%=:\n\t"                                                       \
            "mbarrier.try_wait.parity.acquire.cta.shared::cta.b64 P1, [%0], %1, 0x989680;\n\t" \
            "@P1 bra.uni WD_%=;\n\t"                                           \
            "bra.uni WL_%=;\n\t"                                               \
            "WD_%=:\n\t}" :: "r"(_m), "r"(_p) : "memory");                     \
    } } while (0)

// ---- tiled-swizzled GEMM operand layout (8KB blocks) ------------------------
__device__ __forceinline__ size_t tiled_off(int r, int kchunk, int Kd) {
    int mb = r >> 7, kb = kchunk >> 2;
    int ri = r & 127, ci = kchunk & 3;
    int cs = ci ^ ((ri >> 1) & 3);
    return ((size_t)(mb * (Kd >> 5) + kb)) * 8192 + ri * 64 + cs * 16;
}

// ---- flash ftile / vtile layouts -------------------------------------------
__device__ __forceinline__ size_t ftile_off(int s, int d) {
    return (size_t)s * 256 + (size_t)(((d >> 3) ^ (s & 7)) << 4)
         + (size_t)(d & 7) * 2;
}
__device__ __forceinline__ size_t vtile_off(int d, int s) {
    int cc = s & 63;
    return (size_t)(s >> 6) * 16384 + (size_t)d * 128
         + (size_t)((((cc) >> 3) ^ (d & 7)) << 4) + (size_t)(cc & 7) * 2;
}

// ================= merged prep kernels ======================================
__global__ __launch_bounds__(256)
void split_all(const float* __restrict__ src, const float* __restrict__ hid,
               bf16* __restrict__ sH, bf16* __restrict__ sL,
               bf16* __restrict__ hH, bf16* __restrict__ hL, int n8)
{
    int i = blockIdx.x * blockDim.x + threadIdx.x;
    const float* x; bf16 *hip, *lop;
    if (i >= n8) { i -= n8; x = hid; hip = hH; lop = hL; }
    else         {          x = src; hip = sH; lop = sL; }
    int r  = i >> 8;
    int kc = i & 255;
    const float4* xp = (const float4*)x + (size_t)i * 2;
    float4 v0 = xp[0], v1 = xp[1];
    uint32_t h0,l0,h1,l1,h2,l2,h3,l3;
    split2(v0.x, v0.y, h0, l0); split2(v0.z, v0.w, h1, l1);
    split2(v1.x, v1.y, h2, l2); split2(v1.z, v1.w, h3, l3);
    size_t o = tiled_off(r, kc, 2048);
    *(uint4*)((char*)hip + o) = make_uint4(h0, h1, h2, h3);
    *(uint4*)((char*)lop + o) = make_uint4(l0, l1, l2, l3);
}

__global__ __launch_bounds__(256)
void tsplit_all(const float* W1, const float* W2, const float* Wk,
                const float* Wv, const float* Wq, const float* Wd,
                bf16* T1H, bf16* T1L, bf16* T2H, bf16* T2L,
                bf16* TkH, bf16* TkL, bf16* TvH, bf16* TvL,
                bf16* TqH, bf16* TqL, bf16* TdH, bf16* TdL)
{
    const float* Wt[6] = { W1, W2, Wk, Wv, Wq, Wd };
    bf16* THt[6] = { T1H, T2H, TkH, TvH, TqH, TdH };
    bf16* TLt[6] = { T1L, T2L, TkL, TvL, TqL, TdL };
    const int Ndt[6] = { 2048, 2048, 512, 512, 2048, 2048 };
    int z = blockIdx.z;
    const float* W = Wt[z];
    bf16* TH = THt[z];
    bf16* TL = TLt[z];
    int Nd = Ndt[z];
    int n0 = blockIdx.x * 32;
    if (n0 >= Nd) return;
    int k0 = blockIdx.y * 32;

    __shared__ float tl[32][33];
    int tx = threadIdx.x & 31;
    int ty = threadIdx.x >> 5;
    #pragma unroll
    for (int i = 0; i < 4; i++)
        tl[ty + 8*i][tx] = W[(size_t)(k0 + ty + 8*i) * Nd + n0 + tx];
    __syncthreads();
    #pragma unroll
    for (int i = 0; i < 4; i++) {
        float v = tl[tx][ty + 8*i];
        bf16 h = __float2bfloat16(v);
        int n_ = n0 + ty + 8*i, k_ = k0 + tx;
        size_t o = tiled_off(n_, k_ >> 3, 2048) + (size_t)(k_ & 7) * 2;
        *(bf16*)((char*)TH + o) = h;
        *(bf16*)((char*)TL + o) = __float2bfloat16(v - __bfloat162float(h));
    }
}

// ================= bulk-load split-bf16 tensor GEMM (grouped, 1 tile/CTA) ===
// Tile 128x128, ktile 32, 8 warps (m64 x n32), 3-stage __syncthreads ring,
// 2 CTAs/SM. Launched with grid == numTiles (non-persistent). Two tile
// groups enable the merged K+V launch.
#define TPL   8192
#define TSTG  (4*TPL)                 // 32768
#define NSTG  3
#define TC_SMEM (64 + NSTG*TSTG)      // 98368
#define NKT   (KDIM/32)               // 64 ktiles per tile

#define M_RELU   1
#define M_RES    2
#define M_WRITEC 8
#define M_SPLIT  16
#define M_FSCAT  32
#define M_VSCAT  64

__global__ __launch_bounds__(256, 2)
void bgemm_kernel(const bf16* __restrict__ AH, const bf16* __restrict__ AL,
                  const bf16* __restrict__ B1H, const bf16* __restrict__ B1L,
                  const bf16* __restrict__ B2H, const bf16* __restrict__ B2L,
                  const float* __restrict__ bias1, const float* __restrict__ bias2,
                  const float* __restrict__ res,
                  float* __restrict__ C,
                  bf16* __restrict__ C1H, bf16* __restrict__ C1L,
                  bf16* __restrict__ C2H, bf16* __restrict__ C2L,
                  int N, int mode1, int mode2, int heads,
                  int gx, int tileSplit)
{
    extern __shared__ char smraw[];
    const uint32_t sb   = smem_u32(smraw);
    const uint32_t fulb = sb;
    const uint32_t sb0  = sb + 64;

    const int tid  = threadIdx.x;
    const int wid  = tid >> 5;
    const int lane = tid & 31;
    const int l15  = lane & 15;
    const int lsel = lane >> 4;
    const int warpM = (wid & 1) * 64;
    const int warpN = (wid >> 1) * 32;

    // this CTA's single tile
    const int ti  = blockIdx.x;
    const int grp = (ti >= tileSplit);
    const int tl  = grp ? ti - tileSplit : ti;
    const int bx  = tl % gx, by = tl / gx;
    const bf16* BH = grp ? B2H : B1H;
    const bf16* BL = grp ? B2L : B1L;
    const int mode = grp ? mode2 : mode1;
    const float* bias = grp ? bias2 : bias1;
    bf16* CH = grp ? C2H : C1H;
    bf16* CL = grp ? C2L : C1L;
    const int mBase = by * 128;
    const int nBase = bx * 128;

    if (tid == 0) {
        #pragma unroll
        for (int s = 0; s < NSTG; s++) MBAR_INIT(fulb + s * 8, 1);
    }
    __syncthreads();

    float acc[4][4][4];
    #pragma unroll
    for (int i = 0; i < 4; i++)
        #pragma unroll
        for (int j = 0; j < 4; j++)
            #pragma unroll
            for (int c = 0; c < 4; c++) acc[i][j][c] = 0.f;

#define TLOAD(kt, st_) do {                                                    \
        MBAR_EXPECT(fulb + (st_)*8, (uint32_t)TSTG);                           \
        uint32_t sp_ = sb0 + (st_)*TSTG;                                       \
        size_t ao_ = ((size_t)(by * 64 + (kt))) * TPL;                         \
        size_t bo_ = ((size_t)(bx * 64 + (kt))) * TPL;                         \
        bulkcp(sp_,           (const char*)AH + ao_, TPL, fulb + (st_)*8);     \
        bulkcp(sp_ +   TPL,   (const char*)AL + ao_, TPL, fulb + (st_)*8);     \
        bulkcp(sp_ + 2*TPL,   (const char*)BH + bo_, TPL, fulb + (st_)*8);     \
        bulkcp(sp_ + 3*TPL,   (const char*)BL + bo_, TPL, fulb + (st_)*8);     \
    } while (0)

    if (tid == 0) { TLOAD(0, 0); TLOAD(1, 1); TLOAD(2, 2); }

    for (int kt = 0; kt < NKT; kt++) {
        const int st = kt % NSTG;
        MBAR_WAIT(fulb + st * 8, (kt / NSTG) & 1);
        const uint32_t sp = sb0 + st * TSTG;

        #pragma unroll
        for (int ks = 0; ks < 2; ks++) {
            uint32_t ah[4][4], al[4][4], bh[4][2], bl[4][2];
            #pragma unroll
            for (int mi = 0; mi < 4; mi++) {
                int ar = warpM + mi * 16 + l15;
                uint32_t ad = sp + ar * 64
                            + (((ks * 2 + lsel) ^ ((ar >> 1) & 3)) << 4);
                ldsm4(ah[mi], ad);
                ldsm4(al[mi], ad + TPL);
            }
            #pragma unroll
            for (int n2 = 0; n2 < 2; n2++) {
                int br = warpN + n2 * 16 + l15;
                uint32_t bd = sp + 2*TPL + br * 64
                            + (((ks * 2 + lsel) ^ ((br >> 1) & 3)) << 4);
                uint32_t r[4];
                ldsm4(r, bd);
                bh[2*n2][0]   = r[0]; bh[2*n2][1]   = r[2];
                bh[2*n2+1][0] = r[1]; bh[2*n2+1][1] = r[3];
                ldsm4(r, bd + TPL);
                bl[2*n2][0]   = r[0]; bl[2*n2][1]   = r[2];
                bl[2*n2+1][0] = r[1]; bl[2*n2+1][1] = r[3];
            }
            #pragma unroll
            for (int mi = 0; mi < 4; mi++)
                #pragma unroll
                for (int ni = 0; ni < 4; ni++) {
                    mma_bf16(acc[mi][ni], al[mi], bh[ni]);
                    mma_bf16(acc[mi][ni], ah[mi], bl[ni]);
                    mma_bf16(acc[mi][ni], ah[mi], bh[ni]);
                }
        }

        __syncthreads();
        if (tid == 0 && kt + NSTG < NKT) TLOAD(kt + NSTG, st);
    }
#undef TLOAD

    // -------- epilogue --------
    const int g  = lane >> 2;
    const int t4 = lane & 3;
    const int rw = mBase + warpM + g;
    const int cw = nBase + warpN + 2 * t4;
    #pragma unroll
    for (int mi = 0; mi < 4; mi++) {
        #pragma unroll
        for (int h = 0; h < 2; h++) {
            const int r = rw + mi * 16 + h * 8;
            const int b = r / SEQ, s = r - (r / SEQ) * SEQ;
            #pragma unroll
            for (int ni = 0; ni < 4; ni++) {
                const int c0 = cw + ni * 8;
                float v0 = acc[mi][ni][h*2 + 0] + bias[c0];
                float v1 = acc[mi][ni][h*2 + 1] + bias[c0 + 1];
                if (mode & M_RELU) { v0 = fmaxf(v0, 0.f); v1 = fmaxf(v1, 0.f); }
                if (mode & M_RES) {
                    v0 += res[(size_t)r * N + c0];
                    v1 += res[(size_t)r * N + c0 + 1];
                }
                if (mode & M_WRITEC) {
                    C[(size_t)r * N + c0]     = v0;
                    C[(size_t)r * N + c0 + 1] = v1;
                }
                if (mode & (M_SPLIT | M_FSCAT | M_VSCAT)) {
                    uint32_t hi, lo;
                    split2(v0, v1, hi, lo);
                    if (mode & M_SPLIT) {
                        size_t o = tiled_off(r, c0 >> 3, 2048)
                                 + (size_t)(c0 & 7) * 2;
                        *(uint32_t*)((char*)CH + o) = hi;
                        *(uint32_t*)((char*)CL + o) = lo;
                    } else if (mode & M_FSCAT) {
                        int head = c0 >> 7, d = c0 & 127;
                        size_t hb = ((size_t)(b * heads + head)) * SEQ * HD * 2;
                        size_t o = hb + ftile_off(s, d);
                        *(uint32_t*)((char*)CH + o) = hi;
                        *(uint32_t*)((char*)CL + o) = lo;
                    } else {
                        int head = c0 >> 7, d = c0 & 127;
                        size_t hb = ((size_t)(b * NKV + head)) * HD * SEQ * 2;
                        size_t o0 = hb + vtile_off(d,     s);
                        size_t o1 = hb + vtile_off(d + 1, s);
                        __nv_bfloat162 H = *reinterpret_cast<__nv_bfloat162*>(&hi);
                        __nv_bfloat162 L = *reinterpret_cast<__nv_bfloat162*>(&lo);
                        *(bf16*)((char*)CH + o0) = H.x;
                        *(bf16*)((char*)CH + o1) = H.y;
                        *(bf16*)((char*)CL + o0) = L.x;
                        *(bf16*)((char*)CL + o1) = L.y;
                    }
                }
            }
        }
    }
}

// ================= tensor-core flash attention (big bulk loads) =============
#define OFF_Q  0
#define FQPL   32768
#define OFF_K  (2*FQPL)
#define FKST   32768
#define OFF_V  (OFF_K + 2*FKST)
#define FVST   32768
#define OFF_MB (OFF_V + 2*FVST)
#define FSMEM  (OFF_MB + 64)

__global__ __launch_bounds__(256, 1)
void flash2_kernel(const bf16* __restrict__ QH, const bf16* __restrict__ QL,
                   const bf16* __restrict__ KH, const bf16* __restrict__ KL,
                   const bf16* __restrict__ VtH, const bf16* __restrict__ VtL,
                   bf16* __restrict__ ctxH, bf16* __restrict__ ctxL)
{
    extern __shared__ char smraw[];
    const uint32_t sb  = smem_u32(smraw);
    const uint32_t fmb = sb + OFF_MB;

    const int tid  = threadIdx.x;
    const int wid  = tid >> 5;
    const int lane = tid & 31;
    const int g    = lane >> 2;
    const int t4   = lane & 3;
    const int l15  = lane & 15;
    const int lsel = lane >> 4;

    const int qb = blockIdx.x;
    const int bh = blockIdx.y;
    const int b  = bh / NH;
    const int h  = bh % NH;
    const int kv = b * NKV + (h / GRP);

    const char* Qhb  = (const char*)QH  + (size_t)bh * SEQ * HD * 2;
    const char* Qlb  = (const char*)QL  + (size_t)bh * SEQ * HD * 2;
    const char* Khb  = (const char*)KH  + (size_t)kv * SEQ * HD * 2;
    const char* Klb  = (const char*)KL  + (size_t)kv * SEQ * HD * 2;
    const char* Vthb = (const char*)VtH + (size_t)kv * HD * SEQ * 2;
    const char* Vtlb = (const char*)VtL + (size_t)kv * HD * SEQ * 2;

    if (tid == 0) { MBAR_INIT(fmb, 1); MBAR_INIT(fmb + 8, 1); }
    __syncthreads();

#define LOADKV(kc, st) do { if (tid == 0) {                                    \
        MBAR_EXPECT(fmb + (st)*8, 65536);                                      \
        size_t kb_ = (size_t)(kc) * 256;                                       \
        size_t vb_ = (size_t)((kc) >> 6) * 16384;                              \
        bulkcp(sb + OFF_K + (st)*FKST,          Khb  + kb_, 16384, fmb + (st)*8); \
        bulkcp(sb + OFF_K + (st)*FKST + 16384,  Klb  + kb_, 16384, fmb + (st)*8); \
        bulkcp(sb + OFF_V + (st)*FVST,          Vthb + vb_, 16384, fmb + (st)*8); \
        bulkcp(sb + OFF_V + (st)*FVST + 16384,  Vtlb + vb_, 16384, fmb + (st)*8); \
    } } while (0)

    if (tid == 0) {
        MBAR_EXPECT(fmb, 131072);
        bulkcp(sb + OFF_Q,        Qhb + (size_t)qb * 32768, 32768, fmb);
        bulkcp(sb + OFF_Q + FQPL, Qlb + (size_t)qb * 32768, 32768, fmb);
        bulkcp(sb + OFF_K,          Khb,  16384, fmb);
        bulkcp(sb + OFF_K + 16384,  Klb,  16384, fmb);
        bulkcp(sb + OFF_V,          Vthb, 16384, fmb);
        bulkcp(sb + OFF_V + 16384,  Vtlb, 16384, fmb);
    }

    const int m0r = wid * 16;
    float O[16][4];
    #pragma unroll
    for (int j = 0; j < 16; j++)
        #pragma unroll
        for (int c = 0; c < 4; c++) O[j][c] = 0.f;
    float mrow0 = -1e30f, mrow1 = -1e30f, lrow0 = 0.f, lrow1 = 0.f;
    const float c1 = 0.08838834764831845f * 1.4426950408889634f;

    for (int ic = 0; ic < SEQ / 64; ic++) {
        const int buf = ic & 1;
        if (ic + 1 < SEQ / 64) LOADKV((ic + 1) * 64, buf ^ 1);
        MBAR_WAIT(fmb + buf * 8, (ic >> 1) & 1);

        float s_[8][4];
        #pragma unroll
        for (int j = 0; j < 8; j++)
            #pragma unroll
            for (int c = 0; c < 4; c++) s_[j][c] = 0.f;

        const uint32_t kbase = sb + OFF_K + buf * FKST;
        #pragma unroll
        for (int kk = 0; kk < 8; kk++) {
            uint32_t aH[4], aL[4];
            int qr = m0r + l15;
            uint32_t aoq = (uint32_t)(qr * 256
                         + (((kk * 2 + lsel) ^ (qr & 7)) << 4));
            ldsm4(aH, sb + OFF_Q + aoq);
            ldsm4(aL, sb + OFF_Q + FQPL + aoq);
            #pragma unroll
            for (int j2 = 0; j2 < 4; j2++) {
                int kr = j2 * 16 + l15;
                uint32_t bo = (uint32_t)(kr * 256
                            + (((kk * 2 + lsel) ^ (kr & 7)) << 4));
                uint32_t rH[4], rL[4];
                ldsm4(rH, kbase + bo);
                ldsm4(rL, kbase + 16384 + bo);
                uint32_t bh0[2] = { rH[0], rH[2] }, bh1[2] = { rH[1], rH[3] };
                uint32_t bl0[2] = { rL[0], rL[2] }, bl1[2] = { rL[1], rL[3] };
                mma_bf16(s_[2*j2],   aL, bh0);
                mma_bf16(s_[2*j2],   aH, bl0);
                mma_bf16(s_[2*j2],   aH, bh0);
                mma_bf16(s_[2*j2+1], aL, bh1);
                mma_bf16(s_[2*j2+1], aH, bl1);
                mma_bf16(s_[2*j2+1], aH, bh1);
            }
        }

        float zx0 = -1e30f, zx1 = -1e30f;
        #pragma unroll
        for (int j = 0; j < 8; j++) {
            zx0 = fmaxf(zx0, fmaxf(s_[j][0], s_[j][1]));
            zx1 = fmaxf(zx1, fmaxf(s_[j][2], s_[j][3]));
        }
        zx0 *= c1; zx1 *= c1;
        #pragma unroll
        for (int w = 1; w <= 2; w <<= 1) {
            zx0 = fmaxf(zx0, __shfl_xor_sync(0xffffffffu, zx0, w));
            zx1 = fmaxf(zx1, __shfl_xor_sync(0xffffffffu, zx1, w));
        }
        float mn0 = fmaxf(mrow0, zx0), mn1 = fmaxf(mrow1, zx1);
        float al0 = ex2(mrow0 - mn0),  al1 = ex2(mrow1 - mn1);
        float rs0 = 0.f, rs1 = 0.f;
        #pragma unroll
        for (int j = 0; j < 8; j++) {
            s_[j][0] = ex2(fmaf(s_[j][0], c1, -mn0));
            s_[j][1] = ex2(fmaf(s_[j][1], c1, -mn0));
            s_[j][2] = ex2(fmaf(s_[j][2], c1, -mn1));
            s_[j][3] = ex2(fmaf(s_[j][3], c1, -mn1));
            rs0 += s_[j][0] + s_[j][1];
            rs1 += s_[j][2] + s_[j][3];
        }
        #pragma unroll
        for (int w = 1; w <= 2; w <<= 1) {
            rs0 += __shfl_xor_sync(0xffffffffu, rs0, w);
            rs1 += __shfl_xor_sync(0xffffffffu, rs1, w);
        }
        lrow0 = lrow0 * al0 + rs0;
        lrow1 = lrow1 * al1 + rs1;
        mrow0 = mn0; mrow1 = mn1;

        #pragma unroll
        for (int j = 0; j < 16; j++) {
            O[j][0] *= al0; O[j][1] *= al0;
            O[j][2] *= al1; O[j][3] *= al1;
        }

        uint32_t ph[4][4], pl[4][4];
        #pragma unroll
        for (int kk = 0; kk < 4; kk++) {
            split2(s_[2*kk][0],   s_[2*kk][1],   ph[kk][0], pl[kk][0]);
            split2(s_[2*kk][2],   s_[2*kk][3],   ph[kk][1], pl[kk][1]);
            split2(s_[2*kk+1][0], s_[2*kk+1][1], ph[kk][2], pl[kk][2]);
            split2(s_[2*kk+1][2], s_[2*kk+1][3], ph[kk][3], pl[kk][3]);
        }

        const uint32_t vbase = sb + OFF_V + buf * FVST;
        #pragma unroll
        for (int kk = 0; kk < 4; kk++) {
            #pragma unroll
            for (int j2 = 0; j2 < 8; j2++) {
                int vr = j2 * 16 + l15;
                uint32_t vo = (uint32_t)(vr * 128
                            + (((kk * 2 + lsel) ^ (vr & 7)) << 4));
                uint32_t rH[4], rL[4];
                ldsm4(rH, vbase + vo);
                ldsm4(rL, vbase + 16384 + vo);
                uint32_t bh0[2] = { rH[0], rH[2] }, bh1[2] = { rH[1], rH[3] };
                uint32_t bl0[2] = { rL[0], rL[2] }, bl1[2] = { rL[1], rL[3] };
                mma_bf16(O[2*j2],   pl[kk], bh0);
                mma_bf16(O[2*j2],   ph[kk], bl0);
                mma_bf16(O[2*j2],   ph[kk], bh0);
                mma_bf16(O[2*j2+1], pl[kk], bh1);
                mma_bf16(O[2*j2+1], ph[kk], bl1);
                mma_bf16(O[2*j2+1], ph[kk], bh1);
            }
        }
        __syncthreads();
    }
#undef LOADKV

    const float inv0 = 1.f / lrow0, inv1 = 1.f / lrow1;
    const int q0 = qb * 128 + m0r + g;
    const int q1 = q0 + 8;
    const int row0 = b * SEQ + q0;
    const int row1 = b * SEQ + q1;
    #pragma unroll
    for (int j = 0; j < 16; j++) {
        const int colg = h * HD + j * 8 + 2 * t4;
        uint32_t hi, lo;
        split2(O[j][0] * inv0, O[j][1] * inv0, hi, lo);
        size_t o0 = tiled_off(row0, colg >> 3, 2048) + (size_t)(colg & 7) * 2;
        *(uint32_t*)((char*)ctxH + o0) = hi;
        *(uint32_t*)((char*)ctxL + o0) = lo;
        split2(O[j][2] * inv1, O[j][3] * inv1, hi, lo);
        size_t o1 = tiled_off(row1, colg >> 3, 2048) + (size_t)(colg & 7) * 2;
        *(uint32_t*)((char*)ctxH + o1) = hi;
        *(uint32_t*)((char*)ctxL + o1) = lo;
    }
}

// ---------------- residual + layernorm -------------------------------------
__device__ __forceinline__ float block_sum256(float v, float* sred)
{
    #pragma unroll
    for (int off = 16; off; off >>= 1) v += __shfl_xor_sync(0xffffffffu, v, off);
    int warp = threadIdx.x >> 5;
    if ((threadIdx.x & 31) == 0) sred[warp] = v;
    __syncthreads();
    if (threadIdx.x < 32) {
        float x = (threadIdx.x < 8) ? sred[threadIdx.x] : 0.f;
        #pragma unroll
        for (int off = 4; off; off >>= 1) x += __shfl_xor_sync(0xffffffffu, x, off);
        if (threadIdx.x == 0) sred[0] = x;
    }
    __syncthreads();
    float r = sred[0];
    __syncthreads();
    return r;
}

__global__ __launch_bounds__(256)
void ln_kernel(const float* __restrict__ x, const float* __restrict__ resid,
               const float* __restrict__ gamma, const float* __restrict__ beta,
               float* __restrict__ out)
{
    __shared__ float sred[32];
    const size_t row = blockIdx.x;
    const int tid = threadIdx.x;
    const float* xr = x     + row * HID;
    const float* rr = resid + row * HID;

    float v[8];
    float s = 0.f;
    #pragma unroll
    for (int t = 0; t < 8; t++) {
        int c = tid + t * 256;
        v[t] = xr[c] + rr[c];
        s += v[t];
    }
    float mean = block_sum256(s, sred) * (1.f / HID);

    float s2 = 0.f;
    #pragma unroll
    for (int t = 0; t < 8; t++) { float d = v[t] - mean; s2 += d * d; }
    float var = block_sum256(s2, sred) * (1.f / HID);
    float rstd = rsqrtf(var + 1e-12f);

    float* orow = out + row * HID;
    #pragma unroll
    for (int t = 0; t < 8; t++) {
        int c = tid + t * 256;
        orow[c] = (v[t] - mean) * rstd * gamma[c] + beta[c];
    }
}

// ---------------- launch ----------------------------------------------------
extern "C" void kernel_launch(void* const* d_in, const int* in_sizes, int n_in,
                              void* d_out, int out_size)
{
    const float* hidden = (const float*)d_in[0];
    const float* src    = (const float*)d_in[1];
    const float* Wq = (const float*)d_in[2];
    const float* bq = (const float*)d_in[3];
    const float* Wk = (const float*)d_in[4];
    const float* bk = (const float*)d_in[5];
    const float* Wv = (const float*)d_in[6];
    const float* bv = (const float*)d_in[7];
    const float* Wd = (const float*)d_in[8];
    const float* bd = (const float*)d_in[9];
    const float* W1 = (const float*)d_in[10];
    const float* b1 = (const float*)d_in[11];
    const float* W2 = (const float*)d_in[12];
    const float* b2 = (const float*)d_in[13];
    const float* gamma = (const float*)d_in[14];
    const float* beta  = (const float*)d_in[15];
    float* out = (float*)d_out;

    float *pPl1, *pPre;
    cudaGetSymbolAddress((void**)&pPl1, g_Pl1);
    cudaGetSymbolAddress((void**)&pPre, g_pre);

    bf16 *srcH,*srcL,*hidH,*hidL,*Pl1H,*Pl1L,*PH,*PL,*ctxH,*ctxL;
    bf16 *QH,*QL,*KHp,*KLp,*VtHp,*VtLp;
    cudaGetSymbolAddress((void**)&srcH, g_srcH); cudaGetSymbolAddress((void**)&srcL, g_srcL);
    cudaGetSymbolAddress((void**)&hidH, g_hidH); cudaGetSymbolAddress((void**)&hidL, g_hidL);
    cudaGetSymbolAddress((void**)&Pl1H, g_Pl1H); cudaGetSymbolAddress((void**)&Pl1L, g_Pl1L);
    cudaGetSymbolAddress((void**)&PH,   g_PH);   cudaGetSymbolAddress((void**)&PL,   g_PL);
    cudaGetSymbolAddress((void**)&ctxH, g_ctxH); cudaGetSymbolAddress((void**)&ctxL, g_ctxL);
    cudaGetSymbolAddress((void**)&QH,   g_QH);   cudaGetSymbolAddress((void**)&QL,   g_QL);
    cudaGetSymbolAddress((void**)&KHp,  g_KH);   cudaGetSymbolAddress((void**)&KLp,  g_KL);
    cudaGetSymbolAddress((void**)&VtHp, g_VtH);  cudaGetSymbolAddress((void**)&VtLp, g_VtL);

    bf16 *WqtH,*WqtL,*WktH,*WktL,*WvtH,*WvtL,*WdtH,*WdtL,*W1tH,*W1tL,*W2tH,*W2tL;
    cudaGetSymbolAddress((void**)&WqtH, g_WqtH); cudaGetSymbolAddress((void**)&WqtL, g_WqtL);
    cudaGetSymbolAddress((void**)&WktH, g_WktH); cudaGetSymbolAddress((void**)&WktL, g_WktL);
    cudaGetSymbolAddress((void**)&WvtH, g_WvtH); cudaGetSymbolAddress((void**)&WvtL, g_WvtL);
    cudaGetSymbolAddress((void**)&WdtH, g_WdtH); cudaGetSymbolAddress((void**)&WdtL, g_WdtL);
    cudaGetSymbolAddress((void**)&W1tH, g_W1tH); cudaGetSymbolAddress((void**)&W1tL, g_W1tL);
    cudaGetSymbolAddress((void**)&W2tH, g_W2tH); cudaGetSymbolAddress((void**)&W2tL, g_W2tL);

    cudaFuncSetAttribute(bgemm_kernel, cudaFuncAttributeMaxDynamicSharedMemorySize, TC_SMEM);
    cudaFuncSetAttribute(flash2_kernel, cudaFuncAttributeMaxDynamicSharedMemorySize, FSMEM);

    dim3 blk(256);
    const int n8 = MROWS * HID / 8;

    // launch 0/1: prep
    split_all<<<2 * n8 / 256, blk>>>(src, hidden, srcH, srcL, hidH, hidL, n8);
    tsplit_all<<<dim3(64, 64, 6), blk>>>(W1, W2, Wk, Wv, Wq, Wd,
                                         W1tH, W1tL, W2tH, W2tL,
                                         WktH, WktL, WvtH, WvtL,
                                         WqtH, WqtL, WdtH, WdtL);

    // launch 2: Pl1 = relu(src @ W1 + b1)  [512 tiles, 1 tile/CTA]
    bgemm_kernel<<<512, blk, TC_SMEM>>>(
        srcH, srcL, W1tH, W1tL, W1tH, W1tL, b1, b1, nullptr,
        pPl1, Pl1H, Pl1L, Pl1H, Pl1L,
        HID, M_RELU | M_WRITEC | M_SPLIT, 0, 0, 16, 512);
    // launch 3: P = (Pl1 @ W2 + b2) + Pl1
    bgemm_kernel<<<512, blk, TC_SMEM>>>(
        Pl1H, Pl1L, W2tH, W2tL, W2tH, W2tL, b2, b2, pPl1,
        nullptr, PH, PL, PH, PL,
        HID, M_RES | M_SPLIT, 0, 0, 16, 512);
    // launch 4: merged K (ftile) + V (vtile)  [128+128 tiles, one wave]
    bgemm_kernel<<<256, blk, TC_SMEM>>>(
        PH, PL, WktH, WktL, WvtH, WvtL, bk, bv, nullptr,
        nullptr, KHp, KLp, VtHp, VtLp,
        NKV*HD, M_FSCAT, M_VSCAT, NKV, 4, 128);
    // launch 5: Q -> ftile
    bgemm_kernel<<<512, blk, TC_SMEM>>>(
        hidH, hidL, WqtH, WqtL, WqtH, WqtL, bq, bq, nullptr,
        nullptr, QH, QL, QH, QL,
        HID, M_FSCAT, 0, NH, 16, 512);
    // launch 6: flash attention
    flash2_kernel<<<dim3(SEQ/128, BATCH*NH), blk, FSMEM>>>(
        QH, QL, KHp, KLp, VtHp, VtLp, ctxH, ctxL);
    // launch 7: pre = ctx @ Wd + bd
    bgemm_kernel<<<512, blk, TC_SMEM>>>(
        ctxH, ctxL, WdtH, WdtL, WdtH, WdtL, bd, bd, nullptr,
        pPre, nullptr, nullptr, nullptr, nullptr,
        HID, M_WRITEC, 0, 0, 16, 512);
    // launch 8: out = layernorm(pre + hidden)
    ln_kernel<<<MROWS, 256>>>(pPre, hidden, gamma, beta, out);
}